// round 1
// baseline (speedup 1.0000x reference)
#include <cuda_runtime.h>
#include <math.h>

#define BATCH   8192
#define DIM     256
#define NTOT    5376   // 256 + 1024 + 4096
#define BM      64
#define BN      64
#define BK      32
#define PSTR    68     // padded smem row stride (floats): conflict-free-ish, float4-aligned

__device__ float g_xsq[BATCH];
__device__ float g_wsq[NTOT];
__device__ unsigned long long g_best[3 * BATCH];

// ---------------------------------------------------------------------------
// prep: per-row ||x||^2, per-prototype ||w||^2, init best keys
// one warp per item; items [0,BATCH) -> x rows, [BATCH, BATCH+NTOT) -> protos
// ---------------------------------------------------------------------------
__global__ void som_prep(const float* __restrict__ x,
                         const float* __restrict__ w1,
                         const float* __restrict__ w2,
                         const float* __restrict__ w3) {
    int warp = (blockIdx.x * blockDim.x + threadIdx.x) >> 5;
    int lane = threadIdx.x & 31;
    if (warp < BATCH) {
        const float* p = x + (long)warp * DIM;
        float s = 0.f;
        #pragma unroll
        for (int c = lane; c < DIM; c += 32) { float v = p[c]; s += v * v; }
        #pragma unroll
        for (int o = 16; o; o >>= 1) s += __shfl_xor_sync(0xffffffffu, s, o);
        if (lane == 0) {
            g_xsq[warp] = s;
            g_best[warp]             = ~0ull;
            g_best[BATCH + warp]     = ~0ull;
            g_best[2 * BATCH + warp] = ~0ull;
        }
    } else if (warp < BATCH + NTOT) {
        int n = warp - BATCH;
        const float* p;
        if (n < 256)       p = w1 + (long)n * DIM;
        else if (n < 1280) p = w2 + (long)(n - 256) * DIM;
        else               p = w3 + (long)(n - 1280) * DIM;
        float s = 0.f;
        #pragma unroll
        for (int c = lane; c < DIM; c += 32) { float v = p[c]; s += v * v; }
        #pragma unroll
        for (int o = 16; o; o >>= 1) s += __shfl_xor_sync(0xffffffffu, s, o);
        if (lane == 0) g_wsq[n] = s;
    }
}

// ---------------------------------------------------------------------------
// main: 64x64 tile GEMM (dot products) fused with argmin epilogue
// grid.x = 128 row tiles, grid.y = 84 n-tiles (4 for L1, 16 for L2, 64 for L3)
// ---------------------------------------------------------------------------
__global__ __launch_bounds__(256, 4)
void som_main(const float* __restrict__ x,
              const float* __restrict__ w1,
              const float* __restrict__ w2,
              const float* __restrict__ w3) {
    __shared__ float xs[BK * PSTR];
    __shared__ float ws[BK * PSTR];
    __shared__ unsigned long long sbest[BM];

    int tid = threadIdx.x;
    int yt  = blockIdx.y;

    int level, n0, wsqOff;
    const float* w;
    if (yt < 4)       { level = 0; w = w1; n0 = yt * BN;        wsqOff = 0;    }
    else if (yt < 20) { level = 1; w = w2; n0 = (yt - 4) * BN;  wsqOff = 256;  }
    else              { level = 2; w = w3; n0 = (yt - 20) * BN; wsqOff = 1280; }

    int row0 = blockIdx.x * BM;
    const float* xblk = x + (long)row0 * DIM;
    const float* wblk = w + (long)n0 * DIM;

    int tx = tid & 15;      // 0..15 -> prototype group (4 protos)
    int ty = tid >> 4;      // 0..15 -> row group (4 rows)

    float acc[4][4];
    #pragma unroll
    for (int i = 0; i < 4; i++)
        #pragma unroll
        for (int j = 0; j < 4; j++) acc[i][j] = 0.f;

    for (int k0 = 0; k0 < DIM; k0 += BK) {
        __syncthreads();
        // cooperative load: 64 rows x 8 float4 each for x-tile and w-tile,
        // stored TRANSPOSED: [k][row/col] with padded stride
        #pragma unroll
        for (int l = 0; l < 2; l++) {
            int idx = tid + l * 256;          // 0..511
            int r   = idx >> 3;               // 0..63
            int kv  = idx & 7;                // 0..7 (float4 along k)
            float4 v = *(const float4*)(xblk + (long)r * DIM + k0 + kv * 4);
            xs[(kv * 4 + 0) * PSTR + r] = v.x;
            xs[(kv * 4 + 1) * PSTR + r] = v.y;
            xs[(kv * 4 + 2) * PSTR + r] = v.z;
            xs[(kv * 4 + 3) * PSTR + r] = v.w;
            float4 u = *(const float4*)(wblk + (long)r * DIM + k0 + kv * 4);
            ws[(kv * 4 + 0) * PSTR + r] = u.x;
            ws[(kv * 4 + 1) * PSTR + r] = u.y;
            ws[(kv * 4 + 2) * PSTR + r] = u.z;
            ws[(kv * 4 + 3) * PSTR + r] = u.w;
        }
        __syncthreads();

        #pragma unroll
        for (int kk = 0; kk < BK; kk++) {
            float4 a = *(const float4*)(xs + kk * PSTR + ty * 4);
            float4 b = *(const float4*)(ws + kk * PSTR + tx * 4);
            acc[0][0] += a.x * b.x; acc[0][1] += a.x * b.y; acc[0][2] += a.x * b.z; acc[0][3] += a.x * b.w;
            acc[1][0] += a.y * b.x; acc[1][1] += a.y * b.y; acc[1][2] += a.y * b.z; acc[1][3] += a.y * b.w;
            acc[2][0] += a.z * b.x; acc[2][1] += a.z * b.y; acc[2][2] += a.z * b.z; acc[2][3] += a.z * b.w;
            acc[3][0] += a.w * b.x; acc[3][1] += a.w * b.y; acc[3][2] += a.w * b.z; acc[3][3] += a.w * b.w;
        }
    }

    // epilogue: score = ||x||^2 + ||w||^2 - 2*dot  (>= 0), pack + argmin
    __syncthreads();
    if (tid < BM) sbest[tid] = ~0ull;
    __syncthreads();

    float wsq_c[4];
    #pragma unroll
    for (int j = 0; j < 4; j++) wsq_c[j] = g_wsq[wsqOff + n0 + tx * 4 + j];

    #pragma unroll
    for (int i = 0; i < 4; i++) {
        int r = ty * 4 + i;
        float xsq = g_xsq[row0 + r];
        unsigned long long best = ~0ull;
        #pragma unroll
        for (int j = 0; j < 4; j++) {
            float score = xsq + wsq_c[j] - 2.0f * acc[i][j];
            if (score < 0.f) score = 0.f;   // keep float-bit ordering valid
            unsigned long long key =
                (((unsigned long long)__float_as_uint(score)) << 32) |
                (unsigned int)(n0 + tx * 4 + j);
            if (key < best) best = key;
        }
        atomicMin(&sbest[r], best);
    }
    __syncthreads();

    if (tid < BM)
        atomicMin(&g_best[level * BATCH + row0 + tid], sbest[tid]);
}

// ---------------------------------------------------------------------------
// finalize: one warp per (level,row): exact q_err + coords, write outputs
// out layout (float32): c1[8192,2] c2[8192,2] c3[8192,2] q1[8192] q2[8192] q3[8192]
// ---------------------------------------------------------------------------
__global__ void som_finalize(const float* __restrict__ x,
                             const float* __restrict__ w1,
                             const float* __restrict__ w2,
                             const float* __restrict__ w3,
                             float* __restrict__ out) {
    int pair = (blockIdx.x * blockDim.x + threadIdx.x) >> 5;
    int lane = threadIdx.x & 31;
    if (pair >= 3 * BATCH) return;
    int level = pair / BATCH;
    int row   = pair - level * BATCH;

    unsigned long long key = g_best[pair];
    int n = (int)(key & 0xffffffffu);
    int side = 16 << level;
    const float* w = (level == 0) ? w1 : ((level == 1) ? w2 : w3);
    const float* wr = w + (long)n * DIM;
    const float* xr = x + (long)row * DIM;

    float s = 0.f;
    #pragma unroll
    for (int c = lane; c < DIM; c += 32) {
        float d = xr[c] - wr[c];
        s += d * d;
    }
    #pragma unroll
    for (int o = 16; o; o >>= 1) s += __shfl_xor_sync(0xffffffffu, s, o);

    if (lane == 0) {
        out[level * (2 * BATCH) + 2 * row + 0] = (float)(n / side);
        out[level * (2 * BATCH) + 2 * row + 1] = (float)(n % side);
        out[3 * (2 * BATCH) + level * BATCH + row] = sqrtf(s);
    }
}

// ---------------------------------------------------------------------------
extern "C" void kernel_launch(void* const* d_in, const int* in_sizes, int n_in,
                              void* d_out, int out_size) {
    const float *x = nullptr, *w1 = nullptr, *w2 = nullptr, *w3 = nullptr;
    for (int i = 0; i < n_in; i++) {
        switch (in_sizes[i]) {
            case 8192 * 256: x  = (const float*)d_in[i]; break;
            case 256 * 256:  w1 = (const float*)d_in[i]; break;
            case 1024 * 256: w2 = (const float*)d_in[i]; break;
            case 4096 * 256: w3 = (const float*)d_in[i]; break;
            default: break;
        }
    }
    float* out = (float*)d_out;

    // prep: (8192 + 5376) warps / 8 warps-per-block
    int prepBlocks = (BATCH + NTOT + 7) / 8;
    som_prep<<<prepBlocks, 256>>>(x, w1, w2, w3);

    dim3 grid(BATCH / BM, 84);   // 128 row tiles x (4+16+64) n-tiles
    som_main<<<grid, 256>>>(x, w1, w2, w3);

    // finalize: 3*8192 warps / 8 per block
    som_finalize<<<3 * BATCH / 8, 256>>>(x, w1, w2, w3, out);
}

// round 2
// speedup vs baseline: 1.3371x; 1.3371x over previous
#include <cuda_runtime.h>
#include <math.h>

#define BATCH   8192
#define DIM     256
#define NTOT    5376   // 256 + 1024 + 4096
#define BM      128
#define BN      128
#define BK      32
#define PSTR    132    // padded smem row stride (floats), mult of 4 (16B align)

__device__ float g_xsq[BATCH];
__device__ float g_wsq[NTOT];
__device__ unsigned long long g_best[3 * BATCH];

// packed f32x2 helpers ------------------------------------------------------
#define FMA_F32X2(d, a, b) \
    asm("fma.rn.f32x2 %0, %1, %2, %3;" : "=l"(d) : "l"(a), "l"(b), "l"(d))

#define DUP_F32X2(d, f) do {                                   \
    unsigned int _u = __float_as_uint(f);                      \
    asm("mov.b64 %0, {%1, %1};" : "=l"(d) : "r"(_u));          \
} while (0)

#define UNPACK_F32X2(lo, hi, v) \
    asm("mov.b64 {%0, %1}, %2;" : "=f"(lo), "=f"(hi) : "l"(v))

// ---------------------------------------------------------------------------
// prep: per-row ||x||^2, per-prototype ||w||^2, init best keys
// ---------------------------------------------------------------------------
__global__ void som_prep(const float* __restrict__ x,
                         const float* __restrict__ w1,
                         const float* __restrict__ w2,
                         const float* __restrict__ w3) {
    int warp = (blockIdx.x * blockDim.x + threadIdx.x) >> 5;
    int lane = threadIdx.x & 31;
    if (warp < BATCH) {
        const float* p = x + (long)warp * DIM;
        float s = 0.f;
        #pragma unroll
        for (int c = lane; c < DIM; c += 32) { float v = p[c]; s += v * v; }
        #pragma unroll
        for (int o = 16; o; o >>= 1) s += __shfl_xor_sync(0xffffffffu, s, o);
        if (lane == 0) {
            g_xsq[warp] = s;
            g_best[warp]             = ~0ull;
            g_best[BATCH + warp]     = ~0ull;
            g_best[2 * BATCH + warp] = ~0ull;
        }
    } else if (warp < BATCH + NTOT) {
        int n = warp - BATCH;
        const float* p;
        if (n < 256)       p = w1 + (long)n * DIM;
        else if (n < 1280) p = w2 + (long)(n - 256) * DIM;
        else               p = w3 + (long)(n - 1280) * DIM;
        float s = 0.f;
        #pragma unroll
        for (int c = lane; c < DIM; c += 32) { float v = p[c]; s += v * v; }
        #pragma unroll
        for (int o = 16; o; o >>= 1) s += __shfl_xor_sync(0xffffffffu, s, o);
        if (lane == 0) g_wsq[n] = s;
    }
}

// ---------------------------------------------------------------------------
// main: 128x128 tile, 256 threads, 8x8 micro-tile, packed f32x2 FMA.
// grid.x = 64 row tiles, grid.y = 42 n-tiles (2 L1, 8 L2, 32 L3)
// ---------------------------------------------------------------------------
__global__ __launch_bounds__(256, 2)
void som_main(const float* __restrict__ x,
              const float* __restrict__ w1,
              const float* __restrict__ w2,
              const float* __restrict__ w3) {
    __shared__ __align__(16) float xs[BK * PSTR];
    __shared__ __align__(16) float ws[BK * PSTR];
    __shared__ unsigned long long sbest[BM];

    int tid = threadIdx.x;
    int yt  = blockIdx.y;

    int level, n0, wsqOff;
    const float* w;
    if (yt < 2)       { level = 0; w = w1; n0 = yt * BN;        wsqOff = 0;    }
    else if (yt < 10) { level = 1; w = w2; n0 = (yt - 2) * BN;  wsqOff = 256;  }
    else              { level = 2; w = w3; n0 = (yt - 10) * BN; wsqOff = 1280; }

    int row0 = blockIdx.x * BM;
    const float* xblk = x + (long)row0 * DIM;
    const float* wblk = w + (long)n0 * DIM;

    int tx = tid & 15;      // col group (8 protos)
    int ty = tid >> 4;      // row group (8 rows)

    // acc[i][jp]: row i (0..7), packed col pair jp (cols 2jp, 2jp+1)
    unsigned long long acc[8][4];
    #pragma unroll
    for (int i = 0; i < 8; i++)
        #pragma unroll
        for (int j = 0; j < 4; j++) acc[i][j] = 0ull;

    for (int k0 = 0; k0 < DIM; k0 += BK) {
        __syncthreads();
        // cooperative load, stored TRANSPOSED [k][row/col]:
        // per array: 128 rows x 8 float4 = 1024 float4 -> 4 per thread
        #pragma unroll
        for (int l = 0; l < 4; l++) {
            int idx = tid + l * 256;          // 0..1023
            int r   = idx >> 3;               // 0..127
            int kv  = idx & 7;                // float4 index along k
            float4 v = *(const float4*)(xblk + (long)r * DIM + k0 + kv * 4);
            xs[(kv * 4 + 0) * PSTR + r] = v.x;
            xs[(kv * 4 + 1) * PSTR + r] = v.y;
            xs[(kv * 4 + 2) * PSTR + r] = v.z;
            xs[(kv * 4 + 3) * PSTR + r] = v.w;
            float4 u = *(const float4*)(wblk + (long)r * DIM + k0 + kv * 4);
            ws[(kv * 4 + 0) * PSTR + r] = u.x;
            ws[(kv * 4 + 1) * PSTR + r] = u.y;
            ws[(kv * 4 + 2) * PSTR + r] = u.z;
            ws[(kv * 4 + 3) * PSTR + r] = u.w;
        }
        __syncthreads();

        #pragma unroll
        for (int kk = 0; kk < BK; kk++) {
            // a: 8 row values at this k, each duplicated into both halves
            const float* ar = xs + kk * PSTR + ty * 8;
            float4 af0 = *(const float4*)ar;
            float4 af1 = *(const float4*)(ar + 4);
            unsigned long long ad[8];
            DUP_F32X2(ad[0], af0.x); DUP_F32X2(ad[1], af0.y);
            DUP_F32X2(ad[2], af0.z); DUP_F32X2(ad[3], af0.w);
            DUP_F32X2(ad[4], af1.x); DUP_F32X2(ad[5], af1.y);
            DUP_F32X2(ad[6], af1.z); DUP_F32X2(ad[7], af1.w);
            // b: 8 col values = 4 packed pairs, read packed for free
            const ulonglong2* bp = (const ulonglong2*)(ws + kk * PSTR + tx * 8);
            ulonglong2 b01 = bp[0];
            ulonglong2 b23 = bp[1];
            unsigned long long bd[4] = { b01.x, b01.y, b23.x, b23.y };
            #pragma unroll
            for (int i = 0; i < 8; i++) {
                FMA_F32X2(acc[i][0], ad[i], bd[0]);
                FMA_F32X2(acc[i][1], ad[i], bd[1]);
                FMA_F32X2(acc[i][2], ad[i], bd[2]);
                FMA_F32X2(acc[i][3], ad[i], bd[3]);
            }
        }
    }

    // epilogue: score = ||x||^2 + ||w||^2 - 2*dot, pack + argmin
    __syncthreads();
    if (tid < BM) sbest[tid] = ~0ull;
    __syncthreads();

    float wsq_c[8];
    #pragma unroll
    for (int j = 0; j < 8; j++) wsq_c[j] = g_wsq[wsqOff + n0 + tx * 8 + j];

    #pragma unroll
    for (int i = 0; i < 8; i++) {
        int r = ty * 8 + i;
        float xsq = g_xsq[row0 + r];
        unsigned long long best = ~0ull;
        #pragma unroll
        for (int jp = 0; jp < 4; jp++) {
            float dlo, dhi;
            UNPACK_F32X2(dlo, dhi, acc[i][jp]);
            float s0 = xsq + wsq_c[2 * jp]     - 2.0f * dlo;
            float s1 = xsq + wsq_c[2 * jp + 1] - 2.0f * dhi;
            if (s0 < 0.f) s0 = 0.f;
            if (s1 < 0.f) s1 = 0.f;
            unsigned long long k0 =
                (((unsigned long long)__float_as_uint(s0)) << 32) |
                (unsigned int)(n0 + tx * 8 + 2 * jp);
            unsigned long long k1 =
                (((unsigned long long)__float_as_uint(s1)) << 32) |
                (unsigned int)(n0 + tx * 8 + 2 * jp + 1);
            if (k0 < best) best = k0;
            if (k1 < best) best = k1;
        }
        atomicMin(&sbest[r], best);
    }
    __syncthreads();

    if (tid < BM)
        atomicMin(&g_best[level * BATCH + row0 + tid], sbest[tid]);
}

// ---------------------------------------------------------------------------
// finalize: one warp per (level,row): exact q_err + coords, write outputs
// ---------------------------------------------------------------------------
__global__ void som_finalize(const float* __restrict__ x,
                             const float* __restrict__ w1,
                             const float* __restrict__ w2,
                             const float* __restrict__ w3,
                             float* __restrict__ out) {
    int pair = (blockIdx.x * blockDim.x + threadIdx.x) >> 5;
    int lane = threadIdx.x & 31;
    if (pair >= 3 * BATCH) return;
    int level = pair / BATCH;
    int row   = pair - level * BATCH;

    unsigned long long key = g_best[pair];
    int n = (int)(key & 0xffffffffu);
    int side = 16 << level;
    const float* w = (level == 0) ? w1 : ((level == 1) ? w2 : w3);
    const float* wr = w + (long)n * DIM;
    const float* xr = x + (long)row * DIM;

    float s = 0.f;
    #pragma unroll
    for (int c = lane; c < DIM; c += 32) {
        float d = xr[c] - wr[c];
        s += d * d;
    }
    #pragma unroll
    for (int o = 16; o; o >>= 1) s += __shfl_xor_sync(0xffffffffu, s, o);

    if (lane == 0) {
        out[level * (2 * BATCH) + 2 * row + 0] = (float)(n / side);
        out[level * (2 * BATCH) + 2 * row + 1] = (float)(n % side);
        out[3 * (2 * BATCH) + level * BATCH + row] = sqrtf(s);
    }
}

// ---------------------------------------------------------------------------
extern "C" void kernel_launch(void* const* d_in, const int* in_sizes, int n_in,
                              void* d_out, int out_size) {
    const float *x = nullptr, *w1 = nullptr, *w2 = nullptr, *w3 = nullptr;
    for (int i = 0; i < n_in; i++) {
        switch (in_sizes[i]) {
            case 8192 * 256: x  = (const float*)d_in[i]; break;
            case 256 * 256:  w1 = (const float*)d_in[i]; break;
            case 1024 * 256: w2 = (const float*)d_in[i]; break;
            case 4096 * 256: w3 = (const float*)d_in[i]; break;
            default: break;
        }
    }
    float* out = (float*)d_out;

    int prepBlocks = (BATCH + NTOT + 7) / 8;
    som_prep<<<prepBlocks, 256>>>(x, w1, w2, w3);

    dim3 grid(BATCH / BM, 42);   // 64 row tiles x (2+8+32) n-tiles
    som_main<<<grid, 256>>>(x, w1, w2, w3);

    som_finalize<<<3 * BATCH / 8, 256>>>(x, w1, w2, w3, out);
}

// round 5
// speedup vs baseline: 1.8567x; 1.3886x over previous
#include <cuda_runtime.h>
#include <cuda_bf16.h>
#include <math.h>
#include <stdint.h>

#define BATCH   8192
#define DIM     256
#define NTOT    5376      // 256 + 1024 + 4096
#define KE      768       // extended K: [hi|lo|hi] (x)  vs  [hi|hi|lo] (w)
#define BM      128
#define BN      128
#define NT      42        // n-tiles: 2 (L1) + 8 (L2) + 32 (L3)
#define BK      64
#define NCHUNK  (KE / BK) // 12
#define ASTR    72        // padded smem row stride in bf16 (144B): conflict-free ldmatrix

// dynamic smem layout (bytes)
#define OFF_XSQ  0         // 128 floats
#define OFF_WSQ  512       // 128 floats
#define OFF_RED  1024      // 128 rows x 2 warp_n x 2 keys (ull) = 4096
#define OFF_A0   5120
#define OFF_A1   23552
#define OFF_B0   41984
#define OFF_B1   60416
#define SMEM_TOTAL 78848   // 60416 + 18432

__device__ __align__(16) __nv_bfloat16 g_Xe[BATCH * KE];   // 12.6 MB
__device__ __align__(16) __nv_bfloat16 g_We[NTOT * KE];    //  8.3 MB
__device__ float g_xsq[BATCH];
__device__ float g_wsq[NTOT];
__device__ unsigned long long g_cand[(size_t)BATCH * NT * 2];

// ---------------------------------------------------------------------------
__device__ __forceinline__ uint32_t smem_u32(const void* p) {
    uint32_t a;
    asm("{ .reg .u64 t; cvta.to.shared.u64 t, %1; cvt.u32.u64 %0, t; }"
        : "=r"(a) : "l"(p));
    return a;
}
// monotone float->uint (handles negatives) and inverse
__device__ __forceinline__ unsigned fkey(float f) {
    unsigned u = __float_as_uint(f);
    return (u & 0x80000000u) ? ~u : (u | 0x80000000u);
}
__device__ __forceinline__ float finv(unsigned m) {
    unsigned u = (m & 0x80000000u) ? (m & 0x7fffffffu) : ~m;
    return __uint_as_float(u);
}
__device__ __forceinline__ unsigned long long umin64(unsigned long long a,
                                                     unsigned long long b) {
    return a < b ? a : b;
}
__device__ __forceinline__ unsigned long long umax64(unsigned long long a,
                                                     unsigned long long b) {
    return a > b ? a : b;
}

#define CP16(d, s) \
    asm volatile("cp.async.cg.shared.global [%0], [%1], 16;" :: "r"(d), "l"(s))

#define LDSM_X4(r0, r1, r2, r3, a) \
    asm volatile("ldmatrix.sync.aligned.m8n8.x4.shared.b16 {%0,%1,%2,%3}, [%4];" \
        : "=r"(r0), "=r"(r1), "=r"(r2), "=r"(r3) : "r"(a))

#define MMA16816(d, a, b0, b1) \
    asm volatile("mma.sync.aligned.m16n8k16.row.col.f32.bf16.bf16.f32 " \
        "{%0,%1,%2,%3}, {%4,%5,%6,%7}, {%8,%9}, {%0,%1,%2,%3};" \
        : "+f"((d)[0]), "+f"((d)[1]), "+f"((d)[2]), "+f"((d)[3]) \
        : "r"((a)[0]), "r"((a)[1]), "r"((a)[2]), "r"((a)[3]), \
          "r"(b0), "r"(b1))

// ---------------------------------------------------------------------------
// conv_x: bf16 split [hi|lo|hi] + ||x||^2 (block = one row, 256 threads)
// ---------------------------------------------------------------------------
__global__ void conv_x(const float* __restrict__ x) {
    __shared__ float part[8];
    int r = blockIdx.x, k = threadIdx.x;
    float v = x[(size_t)r * DIM + k];
    __nv_bfloat16 h = __float2bfloat16_rn(v);
    float lof = v - __bfloat162float(h);
    __nv_bfloat16 l = __float2bfloat16_rn(lof);
    size_t b = (size_t)r * KE;
    g_Xe[b + k]       = h;
    g_Xe[b + 256 + k] = l;
    g_Xe[b + 512 + k] = h;
    float s = v * v;
    #pragma unroll
    for (int o = 16; o; o >>= 1) s += __shfl_xor_sync(0xffffffffu, s, o);
    if ((k & 31) == 0) part[k >> 5] = s;
    __syncthreads();
    if (k == 0) {
        float t = 0.f;
        #pragma unroll
        for (int i = 0; i < 8; i++) t += part[i];
        g_xsq[r] = t;
    }
}

// conv_w: bf16 split [hi|hi|lo] + ||w||^2
__global__ void conv_w(const float* __restrict__ w1,
                       const float* __restrict__ w2,
                       const float* __restrict__ w3) {
    __shared__ float part[8];
    int r = blockIdx.x, k = threadIdx.x;
    const float* p;
    if (r < 256)       p = w1 + (size_t)r * DIM;
    else if (r < 1280) p = w2 + (size_t)(r - 256) * DIM;
    else               p = w3 + (size_t)(r - 1280) * DIM;
    float v = p[k];
    __nv_bfloat16 h = __float2bfloat16_rn(v);
    float lof = v - __bfloat162float(h);
    __nv_bfloat16 l = __float2bfloat16_rn(lof);
    size_t b = (size_t)r * KE;
    g_We[b + k]       = h;
    g_We[b + 256 + k] = h;
    g_We[b + 512 + k] = l;
    float s = v * v;
    #pragma unroll
    for (int o = 16; o; o >>= 1) s += __shfl_xor_sync(0xffffffffu, s, o);
    if ((k & 31) == 0) part[k >> 5] = s;
    __syncthreads();
    if (k == 0) {
        float t = 0.f;
        #pragma unroll
        for (int i = 0; i < 8; i++) t += part[i];
        g_wsq[r] = t;
    }
}

// ---------------------------------------------------------------------------
// main: mma.sync bf16 GEMM 128x128 tile, K'=768, double-buffered cp.async,
// fused top-2 argmin per (row, tile). grid = (64, 42), 256 threads (8 warps).
// warp grid 4(m) x 2(n): warp tile 32x64 = 2(m16) x 8(n8) MMAs per k16.
// ---------------------------------------------------------------------------
__device__ __forceinline__ void prefetch_chunk(uint32_t bA, uint32_t bB,
                                               const __nv_bfloat16* gA,
                                               const __nv_bfloat16* gB,
                                               int k0, int tid) {
    #pragma unroll
    for (int it = 0; it < 4; it++) {
        int idx = tid + it * 256;          // 0..1023
        int r = idx >> 3;                  // 0..127
        int g = idx & 7;                   // 16B group within 64 bf16
        uint32_t off = (uint32_t)(r * ASTR + g * 8) * 2;
        CP16(bA + off, gA + (size_t)r * KE + k0 + g * 8);
        CP16(bB + off, gB + (size_t)r * KE + k0 + g * 8);
    }
    asm volatile("cp.async.commit_group;" ::: "memory");
}

__global__ __launch_bounds__(256, 1)
void som_mma() {
    extern __shared__ char smem[];
    float* s_xsq = (float*)(smem + OFF_XSQ);
    float* s_wsq = (float*)(smem + OFF_WSQ);
    unsigned long long* s_red = (unsigned long long*)(smem + OFF_RED);
    uint32_t sb = smem_u32(smem);

    int tid = threadIdx.x, L = tid & 31, wid = tid >> 5;
    int warp_m = wid & 3, warp_n = wid >> 2;
    int yt = blockIdx.y;

    int n0, wsqOff;
    if (yt < 2)       { n0 = yt * BN;        wsqOff = 0;    }
    else if (yt < 10) { n0 = (yt - 2) * BN;  wsqOff = 256;  }
    else              { n0 = (yt - 10) * BN; wsqOff = 1280; }

    int row0 = blockIdx.x * BM;
    const __nv_bfloat16* gA = g_Xe + (size_t)row0 * KE;
    const __nv_bfloat16* gB = g_We + (size_t)(wsqOff + n0) * KE;

    if (tid < 128) {
        s_xsq[tid] = g_xsq[row0 + tid];
        s_wsq[tid] = g_wsq[wsqOff + n0 + tid];
    }

    const uint32_t offA[2] = { OFF_A0, OFF_A1 };
    const uint32_t offB[2] = { OFF_B0, OFF_B1 };

    prefetch_chunk(sb + offA[0], sb + offB[0], gA, gB, 0, tid);
    prefetch_chunk(sb + offA[1], sb + offB[1], gA, gB, BK, tid);

    float acc[2][8][4];
    #pragma unroll
    for (int i = 0; i < 2; i++)
        #pragma unroll
        for (int j = 0; j < 8; j++)
            #pragma unroll
            for (int q = 0; q < 4; q++) acc[i][j][q] = 0.f;

    for (int c = 0; c < NCHUNK; c++) {
        if (c < NCHUNK - 1)
            asm volatile("cp.async.wait_group 1;" ::: "memory");
        else
            asm volatile("cp.async.wait_group 0;" ::: "memory");
        __syncthreads();

        uint32_t bA = sb + offA[c & 1], bB = sb + offB[c & 1];
        #pragma unroll
        for (int kk = 0; kk < 4; kk++) {
            uint32_t a[2][4];
            #pragma unroll
            for (int i = 0; i < 2; i++) {
                int row = warp_m * 32 + i * 16 + (L & 15);
                uint32_t addr = bA + (uint32_t)(row * ASTR + kk * 16 + (L >> 4) * 8) * 2;
                LDSM_X4(a[i][0], a[i][1], a[i][2], a[i][3], addr);
            }
            uint32_t b[8][2];
            #pragma unroll
            for (int jp = 0; jp < 4; jp++) {
                int n = warp_n * 64 + jp * 16 + ((L >> 4) & 1) * 8 + (L & 7);
                uint32_t koff = ((L >> 3) & 1) * 8;
                uint32_t addr = bB + (uint32_t)(n * ASTR + kk * 16 + koff) * 2;
                uint32_t r0, r1, r2, r3;
                LDSM_X4(r0, r1, r2, r3, addr);
                b[2 * jp][0] = r0;     b[2 * jp][1] = r1;
                b[2 * jp + 1][0] = r2; b[2 * jp + 1][1] = r3;
            }
            #pragma unroll
            for (int i = 0; i < 2; i++)
                #pragma unroll
                for (int j = 0; j < 8; j++)
                    MMA16816(acc[i][j], a[i], b[j][0], b[j][1]);
        }
        __syncthreads();
        if (c + 2 < NCHUNK)
            prefetch_chunk(sb + offA[c & 1], sb + offB[c & 1], gA, gB,
                           (c + 2) * BK, tid);
    }

    // ------------- epilogue: scores + per-row top-2 over this tile ----------
    unsigned long long best[4], best2[4];
    #pragma unroll
    for (int r = 0; r < 4; r++) { best[r] = ~0ull; best2[r] = ~0ull; }

    #pragma unroll
    for (int i = 0; i < 2; i++) {
        #pragma unroll
        for (int half = 0; half < 2; half++) {
            int ridx = i * 2 + half;
            int row = warp_m * 32 + i * 16 + (L >> 2) + half * 8;
            float xq = s_xsq[row];
            #pragma unroll
            for (int j = 0; j < 8; j++) {
                int nb = warp_n * 64 + j * 8 + 2 * (L & 3);
                float s0 = xq + s_wsq[nb]     - 2.0f * acc[i][j][half * 2 + 0];
                float s1 = xq + s_wsq[nb + 1] - 2.0f * acc[i][j][half * 2 + 1];
                unsigned long long k0 =
                    (((unsigned long long)fkey(s0)) << 32) | (unsigned)(n0 + nb);
                unsigned long long k1 =
                    (((unsigned long long)fkey(s1)) << 32) | (unsigned)(n0 + nb + 1);
                if (k0 < best[ridx]) { best2[ridx] = best[ridx]; best[ridx] = k0; }
                else if (k0 < best2[ridx]) best2[ridx] = k0;
                if (k1 < best[ridx]) { best2[ridx] = best[ridx]; best[ridx] = k1; }
                else if (k1 < best2[ridx]) best2[ridx] = k1;
            }
        }
    }

    // quad reduction (lanes sharing the same rows: L^1, L^2)
    #pragma unroll
    for (int off = 1; off < 4; off <<= 1) {
        #pragma unroll
        for (int r = 0; r < 4; r++) {
            unsigned long long ob  = __shfl_xor_sync(0xffffffffu, best[r], off);
            unsigned long long ob2 = __shfl_xor_sync(0xffffffffu, best2[r], off);
            unsigned long long lo = umin64(best[r], ob);
            unsigned long long hi = umax64(best[r], ob);
            best[r]  = lo;
            best2[r] = umin64(hi, umin64(best2[r], ob2));
        }
    }
    if ((L & 3) == 0) {
        #pragma unroll
        for (int i = 0; i < 2; i++)
            #pragma unroll
            for (int half = 0; half < 2; half++) {
                int ridx = i * 2 + half;
                int row = warp_m * 32 + i * 16 + (L >> 2) + half * 8;
                s_red[row * 4 + warp_n * 2 + 0] = best[ridx];
                s_red[row * 4 + warp_n * 2 + 1] = best2[ridx];
            }
    }
    __syncthreads();

    if (tid < 128) {
        unsigned long long a1 = s_red[tid * 4 + 0], a2 = s_red[tid * 4 + 1];
        unsigned long long c1 = s_red[tid * 4 + 2], c2 = s_red[tid * 4 + 3];
        unsigned long long b1 = umin64(a1, c1);
        unsigned long long b2 = umin64(umax64(a1, c1), umin64(a2, c2));
        size_t gi = ((size_t)(row0 + tid) * NT + yt) * 2;
        g_cand[gi]     = b1;
        g_cand[gi + 1] = b2;
    }
}

// ---------------------------------------------------------------------------
// stage2: one warp per (level,row). Exact fp32 rescore of candidates within
// delta of approx min; exact argmin (expanded form, tie -> low idx); exact
// q_err from diff form. Writes outputs.
// ---------------------------------------------------------------------------
__global__ void som_stage2(const float* __restrict__ x,
                           const float* __restrict__ w1,
                           const float* __restrict__ w2,
                           const float* __restrict__ w3,
                           float* __restrict__ out) {
    int gw = (blockIdx.x * blockDim.x + threadIdx.x) >> 5;
    int lane = threadIdx.x & 31;
    if (gw >= 3 * BATCH) return;
    int level = gw / BATCH;
    int row = gw - level * BATCH;

    const int t0s[3]  = { 0, 2, 10 };
    const int ncs[3]  = { 4, 16, 64 };
    const int offs[3] = { 0, 256, 1280 };
    int t0 = t0s[level], nc = ncs[level];
    const float* w = (level == 0) ? w1 : ((level == 1) ? w2 : w3);
    int side = 16 << level;

    size_t cbase = ((size_t)row * NT + t0) * 2;
    unsigned long long cand[2] = { ~0ull, ~0ull };
    if (lane < nc)      cand[0] = g_cand[cbase + lane];
    if (lane + 32 < nc) cand[1] = g_cand[cbase + lane + 32];

    const float INF = __int_as_float(0x7f800000);
    float s0 = (cand[0] == ~0ull) ? INF : finv((unsigned)(cand[0] >> 32));
    float s1 = (cand[1] == ~0ull) ? INF : finv((unsigned)(cand[1] >> 32));
    float m = fminf(s0, s1);
    #pragma unroll
    for (int o = 16; o; o >>= 1) m = fminf(m, __shfl_xor_sync(0xffffffffu, m, o));
    float thr = m + 0.25f;

    float xsq = g_xsq[row];
    const float4* xr = (const float4*)(x + (size_t)row * DIM);

    unsigned long long ebest = ~0ull;
    float ed2 = 0.f;
    #pragma unroll
    for (int ci = 0; ci < 2; ci++) {
        unsigned long long k = cand[ci];
        if (k == ~0ull) continue;
        float sc_a = finv((unsigned)(k >> 32));
        if (!(sc_a <= thr)) continue;
        int n = (int)(k & 0xffffffffu);
        const float4* wr = (const float4*)(w + (size_t)n * DIM);
        float dot = 0.f, df = 0.f;
        #pragma unroll 8
        for (int q = 0; q < DIM / 4; q++) {
            float4 a = xr[q], bq = wr[q];
            dot += a.x * bq.x + a.y * bq.y + a.z * bq.z + a.w * bq.w;
            float dx = a.x - bq.x, dy = a.y - bq.y, dz = a.z - bq.z, dw = a.w - bq.w;
            df += dx * dx + dy * dy + dz * dz + dw * dw;
        }
        float sc = xsq + g_wsq[offs[level] + n] - 2.0f * dot;
        unsigned long long ek =
            (((unsigned long long)fkey(sc)) << 32) | (unsigned)n;
        if (ek < ebest) { ebest = ek; ed2 = df; }
    }

    unsigned long long r = ebest;
    #pragma unroll
    for (int o = 16; o; o >>= 1) {
        unsigned long long v = __shfl_xor_sync(0xffffffffu, r, o);
        if (v < r) r = v;
    }
    if (ebest == r && r != ~0ull) {
        int n = (int)(r & 0xffffffffu);
        out[level * (2 * BATCH) + 2 * row + 0] = (float)(n / side);
        out[level * (2 * BATCH) + 2 * row + 1] = (float)(n % side);
        out[3 * (2 * BATCH) + level * BATCH + row] = sqrtf(ed2 < 0.f ? 0.f : ed2);
    }
}

// ---------------------------------------------------------------------------
extern "C" void kernel_launch(void* const* d_in, const int* in_sizes, int n_in,
                              void* d_out, int out_size) {
    const float *x = nullptr, *w1 = nullptr, *w2 = nullptr, *w3 = nullptr;
    for (int i = 0; i < n_in; i++) {
        switch (in_sizes[i]) {
            case 8192 * 256: x  = (const float*)d_in[i]; break;
            case 256 * 256:  w1 = (const float*)d_in[i]; break;
            case 1024 * 256: w2 = (const float*)d_in[i]; break;
            case 4096 * 256: w3 = (const float*)d_in[i]; break;
            default: break;
        }
    }
    float* out = (float*)d_out;

    cudaFuncSetAttribute(som_mma, cudaFuncAttributeMaxDynamicSharedMemorySize,
                         SMEM_TOTAL);

    conv_x<<<BATCH, 256>>>(x);
    conv_w<<<NTOT, 256>>>(w1, w2, w3);

    dim3 grid(BATCH / BM, NT);
    som_mma<<<grid, 256, SMEM_TOTAL>>>();

    som_stage2<<<3 * BATCH / 8, 256>>>(x, w1, w2, w3, out);
}

// round 6
// speedup vs baseline: 2.8532x; 1.5367x over previous
#include <cuda_runtime.h>
#include <cuda_bf16.h>
#include <math.h>
#include <stdint.h>

#define BATCH   8192
#define DIM     256
#define NTOT    5376      // 256 + 1024 + 4096
#define BM      128
#define BN      128
#define NT      42        // n-tiles: 2 (L1) + 8 (L2) + 32 (L3)
#define BK      64
#define NCHUNK  4         // 256 / 64
#define ASTR    72        // padded smem row stride in bf16 (144B)

// dynamic smem layout (bytes)
#define OFF_XSQ  0          // 128 floats
#define OFF_WSQ  512        // 128 floats
#define OFF_RED  1024       // 128 rows x 2 warp_n x 4 keys (ull) = 8192
#define OFF_TILE 9216       // 8 tile buffers of 18432 (A0..A3, B0..B3)
#define TILE_BYTES 18432
#define SMEM_TOTAL (OFF_TILE + 8 * TILE_BYTES)   // 156672

__device__ __align__(16) __nv_bfloat16 g_Xe[BATCH * DIM];   // 4.2 MB
__device__ __align__(16) __nv_bfloat16 g_We[NTOT * DIM];    // 2.75 MB
__device__ float g_xsq[BATCH];
__device__ float g_wsq[NTOT];
__device__ unsigned long long g_cand[(size_t)BATCH * NT * 4];

// ---------------------------------------------------------------------------
__device__ __forceinline__ uint32_t smem_u32(const void* p) {
    uint32_t a;
    asm("{ .reg .u64 t; cvta.to.shared.u64 t, %1; cvt.u32.u64 %0, t; }"
        : "=r"(a) : "l"(p));
    return a;
}
__device__ __forceinline__ unsigned fkey(float f) {
    unsigned u = __float_as_uint(f);
    return (u & 0x80000000u) ? ~u : (u | 0x80000000u);
}
__device__ __forceinline__ float finv(unsigned m) {
    unsigned u = (m & 0x80000000u) ? (m & 0x7fffffffu) : ~m;
    return __uint_as_float(u);
}
__device__ __forceinline__ void ins4(unsigned long long k, unsigned long long t[4]) {
    if (k < t[3]) {
        t[3] = k;
        if (t[3] < t[2]) { unsigned long long z = t[2]; t[2] = t[3]; t[3] = z; }
        if (t[2] < t[1]) { unsigned long long z = t[1]; t[1] = t[2]; t[2] = z; }
        if (t[1] < t[0]) { unsigned long long z = t[0]; t[0] = t[1]; t[1] = z; }
    }
}

#define CP16(d, s) \
    asm volatile("cp.async.cg.shared.global [%0], [%1], 16;" :: "r"(d), "l"(s))

#define LDSM_X4(r0, r1, r2, r3, a) \
    asm volatile("ldmatrix.sync.aligned.m8n8.x4.shared.b16 {%0,%1,%2,%3}, [%4];" \
        : "=r"(r0), "=r"(r1), "=r"(r2), "=r"(r3) : "r"(a))

#define MMA16816(d, a, b0, b1) \
    asm volatile("mma.sync.aligned.m16n8k16.row.col.f32.bf16.bf16.f32 " \
        "{%0,%1,%2,%3}, {%4,%5,%6,%7}, {%8,%9}, {%0,%1,%2,%3};" \
        : "+f"((d)[0]), "+f"((d)[1]), "+f"((d)[2]), "+f"((d)[3]) \
        : "r"((a)[0]), "r"((a)[1]), "r"((a)[2]), "r"((a)[3]), \
          "r"(b0), "r"(b1))

// ---------------------------------------------------------------------------
// conv: bf16 convert + exact fp32 norms. One block per row (x then w).
// ---------------------------------------------------------------------------
__global__ void som_conv(const float* __restrict__ x,
                         const float* __restrict__ w1,
                         const float* __restrict__ w2,
                         const float* __restrict__ w3) {
    __shared__ float part[8];
    int r = blockIdx.x, k = threadIdx.x;
    const float* src;
    __nv_bfloat16* dst;
    float* nrm;
    if (r < BATCH) {
        src = x + (size_t)r * DIM;
        dst = g_Xe + (size_t)r * DIM;
        nrm = g_xsq + r;
    } else {
        int n = r - BATCH;
        if (n < 256)       src = w1 + (size_t)n * DIM;
        else if (n < 1280) src = w2 + (size_t)(n - 256) * DIM;
        else               src = w3 + (size_t)(n - 1280) * DIM;
        dst = g_We + (size_t)n * DIM;
        nrm = g_wsq + n;
    }
    float v = src[k];
    dst[k] = __float2bfloat16_rn(v);
    float s = v * v;
    #pragma unroll
    for (int o = 16; o; o >>= 1) s += __shfl_xor_sync(0xffffffffu, s, o);
    if ((k & 31) == 0) part[k >> 5] = s;
    __syncthreads();
    if (k == 0) {
        float t = 0.f;
        #pragma unroll
        for (int i = 0; i < 8; i++) t += part[i];
        *nrm = t;
    }
}

// ---------------------------------------------------------------------------
// main: mma.sync bf16 GEMM 128x128 tile, K=256 in 4 BK=64 chunks, all 4
// stages prefetched upfront; fused top-4 argmin per (row, tile).
// grid = (64, 42), 256 threads (8 warps), warp grid 4(m) x 2(n).
// ---------------------------------------------------------------------------
__global__ __launch_bounds__(256, 1)
void som_mma() {
    extern __shared__ char smem[];
    float* s_xsq = (float*)(smem + OFF_XSQ);
    float* s_wsq = (float*)(smem + OFF_WSQ);
    unsigned long long* s_red = (unsigned long long*)(smem + OFF_RED);
    uint32_t sb = smem_u32(smem);

    int tid = threadIdx.x, L = tid & 31, wid = tid >> 5;
    int warp_m = wid & 3, warp_n = wid >> 2;
    int yt = blockIdx.y;

    int n0, wsqOff;
    if (yt < 2)       { n0 = yt * BN;        wsqOff = 0;    }
    else if (yt < 10) { n0 = (yt - 2) * BN;  wsqOff = 256;  }
    else              { n0 = (yt - 10) * BN; wsqOff = 1280; }

    int row0 = blockIdx.x * BM;
    const __nv_bfloat16* gA = g_Xe + (size_t)row0 * DIM;
    const __nv_bfloat16* gB = g_We + (size_t)(wsqOff + n0) * DIM;

    if (tid < 128) {
        s_xsq[tid] = g_xsq[row0 + tid];
        s_wsq[tid] = g_wsq[wsqOff + n0 + tid];
    }

    // prefetch all 4 chunks (A then B per chunk; one commit group per chunk)
    #pragma unroll
    for (int c = 0; c < NCHUNK; c++) {
        uint32_t bA = sb + OFF_TILE + c * TILE_BYTES;
        uint32_t bB = sb + OFF_TILE + (4 + c) * TILE_BYTES;
        int k0 = c * BK;
        #pragma unroll
        for (int it = 0; it < 4; it++) {
            int idx = tid + it * 256;          // 0..1023
            int r = idx >> 3;                  // 0..127
            int g = idx & 7;                   // 16B group within 64 bf16
            uint32_t off = (uint32_t)(r * ASTR + g * 8) * 2;
            CP16(bA + off, gA + (size_t)r * DIM + k0 + g * 8);
            CP16(bB + off, gB + (size_t)r * DIM + k0 + g * 8);
        }
        asm volatile("cp.async.commit_group;" ::: "memory");
    }

    float acc[2][8][4];
    #pragma unroll
    for (int i = 0; i < 2; i++)
        #pragma unroll
        for (int j = 0; j < 8; j++)
            #pragma unroll
            for (int q = 0; q < 4; q++) acc[i][j][q] = 0.f;

    #pragma unroll
    for (int c = 0; c < NCHUNK; c++) {
        switch (NCHUNK - 1 - c) {
            case 3: asm volatile("cp.async.wait_group 3;" ::: "memory"); break;
            case 2: asm volatile("cp.async.wait_group 2;" ::: "memory"); break;
            case 1: asm volatile("cp.async.wait_group 1;" ::: "memory"); break;
            default: asm volatile("cp.async.wait_group 0;" ::: "memory"); break;
        }
        __syncthreads();

        uint32_t bA = sb + OFF_TILE + c * TILE_BYTES;
        uint32_t bB = sb + OFF_TILE + (4 + c) * TILE_BYTES;
        #pragma unroll
        for (int kk = 0; kk < 4; kk++) {
            uint32_t a[2][4];
            #pragma unroll
            for (int i = 0; i < 2; i++) {
                int row = warp_m * 32 + i * 16 + (L & 15);
                uint32_t addr = bA + (uint32_t)(row * ASTR + kk * 16 + (L >> 4) * 8) * 2;
                LDSM_X4(a[i][0], a[i][1], a[i][2], a[i][3], addr);
            }
            uint32_t b[8][2];
            #pragma unroll
            for (int jp = 0; jp < 4; jp++) {
                int n = warp_n * 64 + jp * 16 + ((L >> 4) & 1) * 8 + (L & 7);
                uint32_t koff = ((L >> 3) & 1) * 8;
                uint32_t addr = bB + (uint32_t)(n * ASTR + kk * 16 + koff) * 2;
                uint32_t r0, r1, r2, r3;
                LDSM_X4(r0, r1, r2, r3, addr);
                b[2 * jp][0] = r0;     b[2 * jp][1] = r1;
                b[2 * jp + 1][0] = r2; b[2 * jp + 1][1] = r3;
            }
            #pragma unroll
            for (int i = 0; i < 2; i++)
                #pragma unroll
                for (int j = 0; j < 8; j++)
                    MMA16816(acc[i][j], a[i], b[j][0], b[j][1]);
        }
    }

    // ------------- epilogue: scores + per-row top-4 over this tile ----------
    unsigned long long t4[4][4];
    #pragma unroll
    for (int r = 0; r < 4; r++)
        #pragma unroll
        for (int s = 0; s < 4; s++) t4[r][s] = ~0ull;

    #pragma unroll
    for (int i = 0; i < 2; i++) {
        #pragma unroll
        for (int half = 0; half < 2; half++) {
            int ridx = i * 2 + half;
            int row = warp_m * 32 + i * 16 + (L >> 2) + half * 8;
            float xq = s_xsq[row];
            #pragma unroll
            for (int j = 0; j < 8; j++) {
                int nb = warp_n * 64 + j * 8 + 2 * (L & 3);
                float s0 = xq + s_wsq[nb]     - 2.0f * acc[i][j][half * 2 + 0];
                float s1 = xq + s_wsq[nb + 1] - 2.0f * acc[i][j][half * 2 + 1];
                unsigned long long k0 =
                    (((unsigned long long)fkey(s0)) << 32) | (unsigned)(n0 + nb);
                unsigned long long k1 =
                    (((unsigned long long)fkey(s1)) << 32) | (unsigned)(n0 + nb + 1);
                ins4(k0, t4[ridx]);
                ins4(k1, t4[ridx]);
            }
        }
    }

    // quad reduction (lanes L^1, L^2 share the same rows)
    #pragma unroll
    for (int off = 1; off < 4; off <<= 1) {
        #pragma unroll
        for (int r = 0; r < 4; r++) {
            unsigned long long o0 = __shfl_xor_sync(0xffffffffu, t4[r][0], off);
            unsigned long long o1 = __shfl_xor_sync(0xffffffffu, t4[r][1], off);
            unsigned long long o2 = __shfl_xor_sync(0xffffffffu, t4[r][2], off);
            unsigned long long o3 = __shfl_xor_sync(0xffffffffu, t4[r][3], off);
            ins4(o0, t4[r]); ins4(o1, t4[r]); ins4(o2, t4[r]); ins4(o3, t4[r]);
        }
    }
    if ((L & 3) == 0) {
        #pragma unroll
        for (int i = 0; i < 2; i++)
            #pragma unroll
            for (int half = 0; half < 2; half++) {
                int ridx = i * 2 + half;
                int row = warp_m * 32 + i * 16 + (L >> 2) + half * 8;
                #pragma unroll
                for (int s = 0; s < 4; s++)
                    s_red[row * 8 + warp_n * 4 + s] = t4[ridx][s];
            }
    }
    __syncthreads();

    if (tid < 128) {
        unsigned long long m[4];
        #pragma unroll
        for (int s = 0; s < 4; s++) m[s] = s_red[tid * 8 + s];
        #pragma unroll
        for (int s = 0; s < 4; s++) ins4(s_red[tid * 8 + 4 + s], m);
        size_t gi = ((size_t)(row0 + tid) * NT + yt) * 4;
        #pragma unroll
        for (int s = 0; s < 4; s++) g_cand[gi + s] = m[s];
    }
}

// ---------------------------------------------------------------------------
// stage2: one warp per (level,row). Warp-parallel exact fp32 rescore of all
// candidates within thr of approx min; exact argmin + exact q_err; outputs.
// ---------------------------------------------------------------------------
__global__ void som_stage2(const float* __restrict__ x,
                           const float* __restrict__ w1,
                           const float* __restrict__ w2,
                           const float* __restrict__ w3,
                           float* __restrict__ out) {
    int gw = (blockIdx.x * blockDim.x + threadIdx.x) >> 5;
    int lane = threadIdx.x & 31;
    if (gw >= 3 * BATCH) return;
    int level = gw / BATCH;
    int row = gw - level * BATCH;

    const int t0s[3]  = { 0, 2, 10 };
    const int nts[3]  = { 2, 8, 32 };
    const int offs[3] = { 0, 256, 1280 };
    int t0 = t0s[level], ncand = nts[level] * 4;
    const float* w = (level == 0) ? w1 : ((level == 1) ? w2 : w3);
    int side = 16 << level;

    size_t cbase = ((size_t)row * NT + t0) * 4;
    unsigned long long cand[4] = { ~0ull, ~0ull, ~0ull, ~0ull };
    #pragma unroll
    for (int ci = 0; ci < 4; ci++) {
        int idx = lane * 4 + ci;
        if (idx < ncand) cand[ci] = g_cand[cbase + idx];
    }

    const float INF = __int_as_float(0x7f800000);
    float m = INF;
    #pragma unroll
    for (int ci = 0; ci < 4; ci++)
        if (cand[ci] != ~0ull) m = fminf(m, finv((unsigned)(cand[ci] >> 32)));
    #pragma unroll
    for (int o = 16; o; o >>= 1) m = fminf(m, __shfl_xor_sync(0xffffffffu, m, o));
    float thr = m + 1.6f;

    float xsq = g_xsq[row];
    const float4* xr = (const float4*)(x + (size_t)row * DIM);
    float4 xa = xr[lane], xb = xr[lane + 32];

    unsigned long long ebest = ~0ull;
    float ed2 = 0.f;
    #pragma unroll
    for (int ci = 0; ci < 4; ci++) {
        bool pass = (cand[ci] != ~0ull) &&
                    (finv((unsigned)(cand[ci] >> 32)) <= thr);
        unsigned mask = __ballot_sync(0xffffffffu, pass);
        while (mask) {
            int src = __ffs(mask) - 1;
            mask &= mask - 1;
            unsigned long long k = __shfl_sync(0xffffffffu, cand[ci], src);
            int n = (int)(k & 0xffffffffu);
            const float4* wr = (const float4*)(w + (size_t)n * DIM);
            float4 wa = wr[lane], wb = wr[lane + 32];
            float dot = xa.x * wa.x + xa.y * wa.y + xa.z * wa.z + xa.w * wa.w
                      + xb.x * wb.x + xb.y * wb.y + xb.z * wb.z + xb.w * wb.w;
            float dx0 = xa.x - wa.x, dx1 = xa.y - wa.y,
                  dx2 = xa.z - wa.z, dx3 = xa.w - wa.w;
            float dy0 = xb.x - wb.x, dy1 = xb.y - wb.y,
                  dy2 = xb.z - wb.z, dy3 = xb.w - wb.w;
            float df = dx0 * dx0 + dx1 * dx1 + dx2 * dx2 + dx3 * dx3
                     + dy0 * dy0 + dy1 * dy1 + dy2 * dy2 + dy3 * dy3;
            #pragma unroll
            for (int o = 16; o; o >>= 1) {
                dot += __shfl_xor_sync(0xffffffffu, dot, o);
                df  += __shfl_xor_sync(0xffffffffu, df, o);
            }
            float sc = xsq + g_wsq[offs[level] + n] - 2.0f * dot;
            unsigned long long ek =
                (((unsigned long long)fkey(sc)) << 32) | (unsigned)n;
            if (ek < ebest) { ebest = ek; ed2 = df; }
        }
    }

    if (lane == 0) {
        int n = (int)(ebest & 0xffffffffu);
        out[level * (2 * BATCH) + 2 * row + 0] = (float)(n / side);
        out[level * (2 * BATCH) + 2 * row + 1] = (float)(n % side);
        out[3 * (2 * BATCH) + level * BATCH + row] = sqrtf(ed2 < 0.f ? 0.f : ed2);
    }
}

// ---------------------------------------------------------------------------
extern "C" void kernel_launch(void* const* d_in, const int* in_sizes, int n_in,
                              void* d_out, int out_size) {
    const float *x = nullptr, *w1 = nullptr, *w2 = nullptr, *w3 = nullptr;
    for (int i = 0; i < n_in; i++) {
        switch (in_sizes[i]) {
            case 8192 * 256: x  = (const float*)d_in[i]; break;
            case 256 * 256:  w1 = (const float*)d_in[i]; break;
            case 1024 * 256: w2 = (const float*)d_in[i]; break;
            case 4096 * 256: w3 = (const float*)d_in[i]; break;
            default: break;
        }
    }
    float* out = (float*)d_out;

    cudaFuncSetAttribute(som_mma, cudaFuncAttributeMaxDynamicSharedMemorySize,
                         SMEM_TOTAL);

    som_conv<<<BATCH + NTOT, 256>>>(x, w1, w2, w3);

    dim3 grid(BATCH / BM, NT);
    som_mma<<<grid, 256, SMEM_TOTAL>>>();

    som_stage2<<<3 * BATCH / 8, 256>>>(x, w1, w2, w3, out);
}

// round 7
// speedup vs baseline: 4.2749x; 1.4983x over previous
#include <cuda_runtime.h>
#include <cuda_bf16.h>
#include <math.h>
#include <stdint.h>

#define BATCH   8192
#define DIM     256
#define NTOT    5376      // 256 + 1024 + 4096
#define BM      128
#define BN      128
#define NT      42        // n-tiles: 2 (L1) + 8 (L2) + 32 (L3)
#define BK      64
#define NCHUNK  4         // 256 / 64
#define ASTR    72        // padded smem row stride in bf16 (144B)

// dynamic smem layout (bytes)
#define OFF_XSQ  0          // 128 floats
#define OFF_WSQ  512        // 128 floats
#define OFF_RED  1024       // 128 rows x 2 warp_n x 4 keys (ull) = 8192
#define OFF_TILE 9216       // 4 tile buffers: A0, A1, B0, B1
#define TILE_BYTES 18432
#define SMEM_TOTAL (OFF_TILE + 4 * TILE_BYTES)   // 82944 -> 2 CTAs/SM

__device__ __align__(16) __nv_bfloat16 g_Xe[BATCH * DIM];   // 4.2 MB
__device__ __align__(16) __nv_bfloat16 g_We[NTOT * DIM];    // 2.75 MB
__device__ float g_xsq[BATCH];
__device__ float g_wsq[NTOT];
__device__ unsigned long long g_cand[(size_t)BATCH * NT * 4];

// ---------------------------------------------------------------------------
__device__ __forceinline__ uint32_t smem_u32(const void* p) {
    uint32_t a;
    asm("{ .reg .u64 t; cvta.to.shared.u64 t, %1; cvt.u32.u64 %0, t; }"
        : "=r"(a) : "l"(p));
    return a;
}
__device__ __forceinline__ unsigned fkey(float f) {
    unsigned u = __float_as_uint(f);
    return (u & 0x80000000u) ? ~u : (u | 0x80000000u);
}
__device__ __forceinline__ float finv(unsigned m) {
    unsigned u = (m & 0x80000000u) ? (m & 0x7fffffffu) : ~m;
    return __uint_as_float(u);
}
__device__ __forceinline__ void ins4(unsigned long long k, unsigned long long t[4]) {
    if (k < t[3]) {
        t[3] = k;
        if (t[3] < t[2]) { unsigned long long z = t[2]; t[2] = t[3]; t[3] = z; }
        if (t[2] < t[1]) { unsigned long long z = t[1]; t[1] = t[2]; t[2] = z; }
        if (t[1] < t[0]) { unsigned long long z = t[0]; t[0] = t[1]; t[1] = z; }
    }
}

#define CP16(d, s) \
    asm volatile("cp.async.cg.shared.global [%0], [%1], 16;" :: "r"(d), "l"(s))

#define LDSM_X4(r0, r1, r2, r3, a) \
    asm volatile("ldmatrix.sync.aligned.m8n8.x4.shared.b16 {%0,%1,%2,%3}, [%4];" \
        : "=r"(r0), "=r"(r1), "=r"(r2), "=r"(r3) : "r"(a))

#define MMA16816(d, a, b0, b1) \
    asm volatile("mma.sync.aligned.m16n8k16.row.col.f32.bf16.bf16.f32 " \
        "{%0,%1,%2,%3}, {%4,%5,%6,%7}, {%8,%9}, {%0,%1,%2,%3};" \
        : "+f"((d)[0]), "+f"((d)[1]), "+f"((d)[2]), "+f"((d)[3]) \
        : "r"((a)[0]), "r"((a)[1]), "r"((a)[2]), "r"((a)[3]), \
          "r"(b0), "r"(b1))

// ---------------------------------------------------------------------------
// conv: warp per row. 2x float4 loads, packed bf16x2 stores, shfl reduction.
// ---------------------------------------------------------------------------
__global__ void som_conv(const float* __restrict__ x,
                         const float* __restrict__ w1,
                         const float* __restrict__ w2,
                         const float* __restrict__ w3) {
    int gw = (blockIdx.x * blockDim.x + threadIdx.x) >> 5;
    int lane = threadIdx.x & 31;
    if (gw >= BATCH + NTOT) return;
    const float* src;
    __nv_bfloat16* dst;
    float* nrm;
    if (gw < BATCH) {
        src = x + (size_t)gw * DIM;
        dst = g_Xe + (size_t)gw * DIM;
        nrm = g_xsq + gw;
    } else {
        int n = gw - BATCH;
        if (n < 256)       src = w1 + (size_t)n * DIM;
        else if (n < 1280) src = w2 + (size_t)(n - 256) * DIM;
        else               src = w3 + (size_t)(n - 1280) * DIM;
        dst = g_We + (size_t)n * DIM;
        nrm = g_wsq + n;
    }
    float4 a = ((const float4*)src)[lane * 2];
    float4 b = ((const float4*)src)[lane * 2 + 1];
    __nv_bfloat162 h0 = __floats2bfloat162_rn(a.x, a.y);
    __nv_bfloat162 h1 = __floats2bfloat162_rn(a.z, a.w);
    __nv_bfloat162 h2 = __floats2bfloat162_rn(b.x, b.y);
    __nv_bfloat162 h3 = __floats2bfloat162_rn(b.z, b.w);
    uint4 pk;
    pk.x = *(unsigned*)&h0; pk.y = *(unsigned*)&h1;
    pk.z = *(unsigned*)&h2; pk.w = *(unsigned*)&h3;
    ((uint4*)dst)[lane] = pk;
    float s = a.x * a.x + a.y * a.y + a.z * a.z + a.w * a.w
            + b.x * b.x + b.y * b.y + b.z * b.z + b.w * b.w;
    #pragma unroll
    for (int o = 16; o; o >>= 1) s += __shfl_xor_sync(0xffffffffu, s, o);
    if (lane == 0) *nrm = s;
}

// ---------------------------------------------------------------------------
// main: mma.sync bf16 GEMM 128x128 tile, K=256 in 4 BK=64 chunks,
// 2-stage double-buffered cp.async (2 CTAs/SM); fused top-4 argmin per tile.
// grid = (64, 42), 256 threads (8 warps), warp grid 4(m) x 2(n).
// ---------------------------------------------------------------------------
__device__ __forceinline__ void prefetch_chunk(uint32_t bA, uint32_t bB,
                                               const __nv_bfloat16* gA,
                                               const __nv_bfloat16* gB,
                                               int k0, int tid) {
    #pragma unroll
    for (int it = 0; it < 4; it++) {
        int idx = tid + it * 256;          // 0..1023
        int r = idx >> 3;                  // 0..127
        int g = idx & 7;                   // 16B group within 64 bf16
        uint32_t off = (uint32_t)(r * ASTR + g * 8) * 2;
        CP16(bA + off, gA + (size_t)r * DIM + k0 + g * 8);
        CP16(bB + off, gB + (size_t)r * DIM + k0 + g * 8);
    }
    asm volatile("cp.async.commit_group;" ::: "memory");
}

__global__ __launch_bounds__(256, 2)
void som_mma() {
    extern __shared__ char smem[];
    float* s_xsq = (float*)(smem + OFF_XSQ);
    float* s_wsq = (float*)(smem + OFF_WSQ);
    unsigned long long* s_red = (unsigned long long*)(smem + OFF_RED);
    uint32_t sb = smem_u32(smem);

    int tid = threadIdx.x, L = tid & 31, wid = tid >> 5;
    int warp_m = wid & 3, warp_n = wid >> 2;
    int yt = blockIdx.y;

    int n0, wsqOff;
    if (yt < 2)       { n0 = yt * BN;        wsqOff = 0;    }
    else if (yt < 10) { n0 = (yt - 2) * BN;  wsqOff = 256;  }
    else              { n0 = (yt - 10) * BN; wsqOff = 1280; }

    int row0 = blockIdx.x * BM;
    const __nv_bfloat16* gA = g_Xe + (size_t)row0 * DIM;
    const __nv_bfloat16* gB = g_We + (size_t)(wsqOff + n0) * DIM;

    if (tid < 128) {
        s_xsq[tid] = g_xsq[row0 + tid];
        s_wsq[tid] = g_wsq[wsqOff + n0 + tid];
    }

    const uint32_t offA[2] = { OFF_TILE,                  OFF_TILE + TILE_BYTES };
    const uint32_t offB[2] = { OFF_TILE + 2 * TILE_BYTES, OFF_TILE + 3 * TILE_BYTES };

    prefetch_chunk(sb + offA[0], sb + offB[0], gA, gB, 0, tid);
    prefetch_chunk(sb + offA[1], sb + offB[1], gA, gB, BK, tid);

    float acc[2][8][4];
    #pragma unroll
    for (int i = 0; i < 2; i++)
        #pragma unroll
        for (int j = 0; j < 8; j++)
            #pragma unroll
            for (int q = 0; q < 4; q++) acc[i][j][q] = 0.f;

    #pragma unroll
    for (int c = 0; c < NCHUNK; c++) {
        if (c < NCHUNK - 1)
            asm volatile("cp.async.wait_group 1;" ::: "memory");
        else
            asm volatile("cp.async.wait_group 0;" ::: "memory");
        __syncthreads();

        uint32_t bA = sb + offA[c & 1], bB = sb + offB[c & 1];
        #pragma unroll
        for (int kk = 0; kk < 4; kk++) {
            uint32_t a[2][4];
            #pragma unroll
            for (int i = 0; i < 2; i++) {
                int row = warp_m * 32 + i * 16 + (L & 15);
                uint32_t addr = bA + (uint32_t)(row * ASTR + kk * 16 + (L >> 4) * 8) * 2;
                LDSM_X4(a[i][0], a[i][1], a[i][2], a[i][3], addr);
            }
            uint32_t b[8][2];
            #pragma unroll
            for (int jp = 0; jp < 4; jp++) {
                int n = warp_n * 64 + jp * 16 + ((L >> 4) & 1) * 8 + (L & 7);
                uint32_t koff = ((L >> 3) & 1) * 8;
                uint32_t addr = bB + (uint32_t)(n * ASTR + kk * 16 + koff) * 2;
                uint32_t r0, r1, r2, r3;
                LDSM_X4(r0, r1, r2, r3, addr);
                b[2 * jp][0] = r0;     b[2 * jp][1] = r1;
                b[2 * jp + 1][0] = r2; b[2 * jp + 1][1] = r3;
            }
            #pragma unroll
            for (int i = 0; i < 2; i++)
                #pragma unroll
                for (int j = 0; j < 8; j++)
                    MMA16816(acc[i][j], a[i], b[j][0], b[j][1]);
        }
        __syncthreads();
        if (c + 2 < NCHUNK)
            prefetch_chunk(sb + offA[c & 1], sb + offB[c & 1], gA, gB,
                           (c + 2) * BK, tid);
    }

    // ------------- epilogue: scores + per-row top-4 over this tile ----------
    unsigned long long t4[4][4];
    #pragma unroll
    for (int r = 0; r < 4; r++)
        #pragma unroll
        for (int s = 0; s < 4; s++) t4[r][s] = ~0ull;

    #pragma unroll
    for (int i = 0; i < 2; i++) {
        #pragma unroll
        for (int half = 0; half < 2; half++) {
            int ridx = i * 2 + half;
            int row = warp_m * 32 + i * 16 + (L >> 2) + half * 8;
            float xq = s_xsq[row];
            #pragma unroll
            for (int j = 0; j < 8; j++) {
                int nb = warp_n * 64 + j * 8 + 2 * (L & 3);
                float s0 = xq + s_wsq[nb]     - 2.0f * acc[i][j][half * 2 + 0];
                float s1 = xq + s_wsq[nb + 1] - 2.0f * acc[i][j][half * 2 + 1];
                unsigned long long k0 =
                    (((unsigned long long)fkey(s0)) << 32) | (unsigned)(n0 + nb);
                unsigned long long k1 =
                    (((unsigned long long)fkey(s1)) << 32) | (unsigned)(n0 + nb + 1);
                ins4(k0, t4[ridx]);
                ins4(k1, t4[ridx]);
            }
        }
    }

    // quad reduction (lanes L^1, L^2 share the same rows)
    #pragma unroll
    for (int off = 1; off < 4; off <<= 1) {
        #pragma unroll
        for (int r = 0; r < 4; r++) {
            unsigned long long o0 = __shfl_xor_sync(0xffffffffu, t4[r][0], off);
            unsigned long long o1 = __shfl_xor_sync(0xffffffffu, t4[r][1], off);
            unsigned long long o2 = __shfl_xor_sync(0xffffffffu, t4[r][2], off);
            unsigned long long o3 = __shfl_xor_sync(0xffffffffu, t4[r][3], off);
            ins4(o0, t4[r]); ins4(o1, t4[r]); ins4(o2, t4[r]); ins4(o3, t4[r]);
        }
    }
    if ((L & 3) == 0) {
        #pragma unroll
        for (int i = 0; i < 2; i++)
            #pragma unroll
            for (int half = 0; half < 2; half++) {
                int ridx = i * 2 + half;
                int row = warp_m * 32 + i * 16 + (L >> 2) + half * 8;
                #pragma unroll
                for (int s = 0; s < 4; s++)
                    s_red[row * 8 + warp_n * 4 + s] = t4[ridx][s];
            }
    }
    __syncthreads();

    if (tid < 128) {
        unsigned long long m[4];
        #pragma unroll
        for (int s = 0; s < 4; s++) m[s] = s_red[tid * 8 + s];
        #pragma unroll
        for (int s = 0; s < 4; s++) ins4(s_red[tid * 8 + 4 + s], m);
        size_t gi = ((size_t)(row0 + tid) * NT + yt) * 4;
        #pragma unroll
        for (int s = 0; s < 4; s++) g_cand[gi + s] = m[s];
    }
}

// ---------------------------------------------------------------------------
// stage2: one warp per (level,row). Warp-parallel exact fp32 rescore of all
// candidates within thr of approx min; exact argmin + exact q_err; outputs.
// ---------------------------------------------------------------------------
__global__ void som_stage2(const float* __restrict__ x,
                           const float* __restrict__ w1,
                           const float* __restrict__ w2,
                           const float* __restrict__ w3,
                           float* __restrict__ out) {
    int gw = (blockIdx.x * blockDim.x + threadIdx.x) >> 5;
    int lane = threadIdx.x & 31;
    if (gw >= 3 * BATCH) return;
    int level = gw / BATCH;
    int row = gw - level * BATCH;

    const int t0s[3]  = { 0, 2, 10 };
    const int nts[3]  = { 2, 8, 32 };
    const int offs[3] = { 0, 256, 1280 };
    int t0 = t0s[level], ncand = nts[level] * 4;
    const float* w = (level == 0) ? w1 : ((level == 1) ? w2 : w3);
    int side = 16 << level;

    size_t cbase = ((size_t)row * NT + t0) * 4;
    unsigned long long cand[4] = { ~0ull, ~0ull, ~0ull, ~0ull };
    #pragma unroll
    for (int ci = 0; ci < 4; ci++) {
        int idx = lane * 4 + ci;
        if (idx < ncand) cand[ci] = g_cand[cbase + idx];
    }

    const float INF = __int_as_float(0x7f800000);
    float m = INF;
    #pragma unroll
    for (int ci = 0; ci < 4; ci++)
        if (cand[ci] != ~0ull) m = fminf(m, finv((unsigned)(cand[ci] >> 32)));
    #pragma unroll
    for (int o = 16; o; o >>= 1) m = fminf(m, __shfl_xor_sync(0xffffffffu, m, o));
    float thr = m + 1.6f;

    float xsq = g_xsq[row];
    const float4* xr = (const float4*)(x + (size_t)row * DIM);
    float4 xa = xr[lane], xb = xr[lane + 32];

    unsigned long long ebest = ~0ull;
    float ed2 = 0.f;
    #pragma unroll
    for (int ci = 0; ci < 4; ci++) {
        bool pass = (cand[ci] != ~0ull) &&
                    (finv((unsigned)(cand[ci] >> 32)) <= thr);
        unsigned mask = __ballot_sync(0xffffffffu, pass);
        while (mask) {
            int src = __ffs(mask) - 1;
            mask &= mask - 1;
            unsigned long long k = __shfl_sync(0xffffffffu, cand[ci], src);
            int n = (int)(k & 0xffffffffu);
            const float4* wr = (const float4*)(w + (size_t)n * DIM);
            float4 wa = wr[lane], wb = wr[lane + 32];
            float dot = xa.x * wa.x + xa.y * wa.y + xa.z * wa.z + xa.w * wa.w
                      + xb.x * wb.x + xb.y * wb.y + xb.z * wb.z + xb.w * wb.w;
            float dx0 = xa.x - wa.x, dx1 = xa.y - wa.y,
                  dx2 = xa.z - wa.z, dx3 = xa.w - wa.w;
            float dy0 = xb.x - wb.x, dy1 = xb.y - wb.y,
                  dy2 = xb.z - wb.z, dy3 = xb.w - wb.w;
            float df = dx0 * dx0 + dx1 * dx1 + dx2 * dx2 + dx3 * dx3
                     + dy0 * dy0 + dy1 * dy1 + dy2 * dy2 + dy3 * dy3;
            #pragma unroll
            for (int o = 16; o; o >>= 1) {
                dot += __shfl_xor_sync(0xffffffffu, dot, o);
                df  += __shfl_xor_sync(0xffffffffu, df, o);
            }
            float sc = xsq + g_wsq[offs[level] + n] - 2.0f * dot;
            unsigned long long ek =
                (((unsigned long long)fkey(sc)) << 32) | (unsigned)n;
            if (ek < ebest) { ebest = ek; ed2 = df; }
        }
    }

    if (lane == 0) {
        int n = (int)(ebest & 0xffffffffu);
        out[level * (2 * BATCH) + 2 * row + 0] = (float)(n / side);
        out[level * (2 * BATCH) + 2 * row + 1] = (float)(n % side);
        out[3 * (2 * BATCH) + level * BATCH + row] = sqrtf(ed2 < 0.f ? 0.f : ed2);
    }
}

// ---------------------------------------------------------------------------
extern "C" void kernel_launch(void* const* d_in, const int* in_sizes, int n_in,
                              void* d_out, int out_size) {
    const float *x = nullptr, *w1 = nullptr, *w2 = nullptr, *w3 = nullptr;
    for (int i = 0; i < n_in; i++) {
        switch (in_sizes[i]) {
            case 8192 * 256: x  = (const float*)d_in[i]; break;
            case 256 * 256:  w1 = (const float*)d_in[i]; break;
            case 1024 * 256: w2 = (const float*)d_in[i]; break;
            case 4096 * 256: w3 = (const float*)d_in[i]; break;
            default: break;
        }
    }
    float* out = (float*)d_out;

    cudaFuncSetAttribute(som_mma, cudaFuncAttributeMaxDynamicSharedMemorySize,
                         SMEM_TOTAL);

    som_conv<<<(BATCH + NTOT + 7) / 8, 256>>>(x, w1, w2, w3);

    dim3 grid(BATCH / BM, NT);
    som_mma<<<grid, 256, SMEM_TOTAL>>>();

    som_stage2<<<3 * BATCH / 8, 256>>>(x, w1, w2, w3, out);
}